// round 17
// baseline (speedup 1.0000x reference)
#include <cuda_runtime.h>
#include <stdint.h>

// ---- problem constants ----
#define NT     512
#define NB     8          // b per CTA
#define ROWS   512        // NB * 64 rows per CTA
#define DIM    40
#define NPAIR  820
#define KP2    960        // padded pairs: each i-run padded to multiple of 8
#define XST    520        // xst row stride (floats): 520%32=8 -> conflict-free xj loads
#define BST    24         // Bs row stride: q*24%32 = {0,24,16,8} -> conflict-free B frags
#define BAS    18         // basis row stride (floats)

// ---- staged tables (filled by prep_kernel) ----
// k-order: runs grouped by i (i outer), j consecutive from i, each run padded
// to a multiple of 8 rows with zero-coefficient rows.
__device__ float g_B[KP2 * 16];    // B[k][n]: tf32-rounded folded U2 coeffs
__device__ float g_u1[DIM * 16];   // U1 rows (13 coeffs + pad)
__constant__ float c_u1t[DIM * 16];

__global__ void prep_kernel(const float* __restrict__ U2_0,
                            const float* __restrict__ U1_0,
                            const float* __restrict__ U2_1,
                            const float* __restrict__ U1_1,
                            const float* __restrict__ U2_2,
                            const float* __restrict__ U1_2) {
    int idx = blockIdx.x * blockDim.x + threadIdx.x;
    if (idx >= KP2 + DIM) return;

    if (idx < KP2) {
        // locate (i, u) for padded-run layout: span(i) = ceil((40-i)/8)*8
        int i = 0, base = 0;
        for (;;) {
            int span = ((DIM - i + 7) >> 3) << 3;
            if (idx < base + span) break;
            base += span; i++;
        }
        int u = idx - base;              // position within padded run
        float row[16];
#pragma unroll
        for (int k = 0; k < 16; k++) row[k] = 0.0f;
        if (u < DIM - i) {               // real pair (i, j)
            int j = i + u;
            const float* U2b[3] = {U2_0, U2_1, U2_2};
#pragma unroll
            for (int m = 0; m < 13; m++) {
                int l  = (m == 0) ? 0 : ((m < 4) ? 1 : 2);
                int mm = (m == 0) ? 0 : ((m < 4) ? (m - 1) : (m - 4));
                const float* U = U2b[l];
                float v = U[(mm * DIM + i) * DIM + j];
                if (i != j) v += U[(mm * DIM + j) * DIM + i];
                unsigned int o;
                asm("cvt.rna.tf32.f32 %0, %1;" : "=r"(o) : "f"(v));
                row[m] = __uint_as_float(o);
            }
        }
#pragma unroll
        for (int k = 0; k < 16; k++) g_B[idx * 16 + k] = row[k];
    } else {
        int i = idx - KP2;
        float row[16];
#pragma unroll
        for (int k = 0; k < 16; k++) row[k] = 0.0f;
        const float* U1b[3] = {U1_0, U1_1, U1_2};
#pragma unroll
        for (int m = 0; m < 13; m++) {
            int l  = (m == 0) ? 0 : ((m < 4) ? 1 : 2);
            int mm = (m == 0) ? 0 : ((m < 4) ? (m - 1) : (m - 4));
            row[m] = U1b[l][mm * DIM + i];
        }
#pragma unroll
        for (int k = 0; k < 16; k++) g_u1[i * 16 + k] = row[k];
    }
}

// ---- packed f32x2 helpers (for the a1 phase) ----
__device__ __forceinline__ void fma2(unsigned long long& acc,
                                     unsigned long long u,
                                     unsigned long long y) {
    asm("fma.rn.f32x2 %0, %1, %2, %0;" : "+l"(acc) : "l"(u), "l"(y));
}
__device__ __forceinline__ unsigned long long dup2(float y) {
    unsigned long long r;
    asm("mov.b64 %0, {%1, %1};" : "=l"(r) : "f"(y));
    return r;
}
__device__ __forceinline__ float2 unpk2(unsigned long long v) {
    float2 r;
    asm("mov.b64 {%0, %1}, %2;" : "=f"(r.x), "=f"(r.y) : "l"(v));
    return r;
}

// ---- tf32 mma.sync m16n8k8 ----
__device__ __forceinline__ void mma_tf32(float* c,
                                         float a0, float a1, float a2, float a3,
                                         float b0, float b1) {
    asm volatile(
        "mma.sync.aligned.m16n8k8.row.col.f32.tf32.tf32.f32 "
        "{%0,%1,%2,%3},{%4,%5,%6,%7},{%8,%9},{%0,%1,%2,%3};"
        : "+f"(c[0]), "+f"(c[1]), "+f"(c[2]), "+f"(c[3])
        : "r"(__float_as_uint(a0)), "r"(__float_as_uint(a1)),
          "r"(__float_as_uint(a2)), "r"(__float_as_uint(a3)),
          "r"(__float_as_uint(b0)), "r"(__float_as_uint(b1)));
}

// SMEM layout (floats):
//   [0,     20800)  xst: x[40][520]  (rows 0..511 used)   -> later Wlin (12288)
//   [20800, 43840)  Bs:  B[960][24]                       -> later basis[512][18]
#define XST_OFF 0
#define BS_OFF  20800
#define SMEM_FLOATS 43840
#define SMEM_BYTES  (SMEM_FLOATS * 4)

__global__ __launch_bounds__(NT, 1)
void main_kernel(const float* __restrict__ f0,  const float* __restrict__ f1,
                 const float* __restrict__ f2,  const float* __restrict__ f3,
                 const float* __restrict__ attrs,
                 const float* __restrict__ W1_0, const float* __restrict__ W2_0,
                 const float* __restrict__ Wl0,  const float* __restrict__ sc0,
                 const float* __restrict__ W1_1, const float* __restrict__ W2_1,
                 const float* __restrict__ Wl1,  const float* __restrict__ sc1,
                 const float* __restrict__ W1_2, const float* __restrict__ W2_2,
                 const float* __restrict__ Wl2,  const float* __restrict__ sc2,
                 float* __restrict__ out, int B) {
    extern __shared__ float S[];
    float* xst = S + XST_OFF;
    float* BsS = S + BS_OFF;
    float* bas = S + BS_OFF;      // reuse after mma
    float* wlS = S + XST_OFF;     // reuse after a1

    const int tid  = threadIdx.x;
    const int lane = tid & 31;
    const int wid  = tid >> 5;    // 0..15

    // ---- cooperative loads ----
    for (int t = tid; t < KP2 * 16; t += NT) {
        int k = t >> 4, n = t & 15;
        BsS[k * BST + n] = g_B[t];
    }

    // x gather: one row per thread
    {
        const int row = tid;
        int bb = blockIdx.x * NB + (row >> 6); if (bb >= B) bb = B - 1;
        const int base = bb * 64 + (row & 63);
        xst[0 * XST + row] = f0[base];
#pragma unroll
        for (int k = 0; k < 3; k++)  xst[(1 + k) * XST + row]  = f1[base * 3 + k];
#pragma unroll
        for (int k = 0; k < 9; k++)  xst[(4 + k) * XST + row]  = f2[base * 9 + k];
#pragma unroll
        for (int k = 0; k < 27; k++) xst[(13 + k) * XST + row] = f3[base * 27 + k];
    }
    __syncthreads();

    // ---- tensor phase: a2 = Y(x) @ U2fold via mma.sync tf32 ----
    // 16 warps, each owns rows [wid*32, wid*32+32): 2 m16-tiles; N=16.
    const int q   = lane & 3;
    const int gid = lane >> 2;
    const int R0  = wid * 32;

    float cfr[2][2][4];
#pragma unroll
    for (int t = 0; t < 2; t++)
#pragma unroll
        for (int n = 0; n < 2; n++)
#pragma unroll
            for (int k = 0; k < 4; k++) cfr[t][n][k] = 0.0f;

    {
        const float* Bp = BsS;
        for (int i = 0; i < DIM; i++) {
            // hoist xi per row-tile (same i for the whole run)
            float xi0[2], xi1[2];
#pragma unroll
            for (int t = 0; t < 2; t++) {
                int r = R0 + t * 16 + gid;
                xi0[t] = xst[i * XST + r];
                xi1[t] = xst[i * XST + r + 8];
            }
            const int nks = (DIM - i + 7) >> 3;
            int jb = i;
            for (int s = 0; s < nks; s++) {
                int j1 = jb + q;     if (j1 > DIM - 1) j1 = DIM - 1;
                int j2 = jb + q + 4; if (j2 > DIM - 1) j2 = DIM - 1;
                const float* xj1 = xst + j1 * XST;
                const float* xj2 = xst + j2 * XST;
                float b00 = Bp[q * BST + gid];
                float b10 = Bp[(q + 4) * BST + gid];
                float b01 = Bp[q * BST + gid + 8];
                float b11 = Bp[(q + 4) * BST + gid + 8];
#pragma unroll
                for (int t = 0; t < 2; t++) {
                    const int r = R0 + t * 16 + gid;
                    float a0  = xi0[t] * xj1[r];
                    float a1v = xi1[t] * xj1[r + 8];
                    float a2v = xi0[t] * xj2[r];
                    float a3v = xi1[t] * xj2[r + 8];
                    mma_tf32(cfr[t][0], a0, a1v, a2v, a3v, b00, b10);
                    mma_tf32(cfr[t][1], a0, a1v, a2v, a3v, b01, b11);
                }
                Bp += 8 * BST;
                jb += 8;
            }
        }
    }
    __syncthreads();   // everyone done reading Bs before overwrite with basis

    // store C frags: bas[row][col], col = nt*8 + 2q (+1)
#pragma unroll
    for (int t = 0; t < 2; t++)
#pragma unroll
        for (int nt = 0; nt < 2; nt++) {
            const int row  = R0 + t * 16 + gid;
            const int colb = nt * 8 + 2 * q;
            *(float2*)&bas[row * BAS + colb]       = make_float2(cfr[t][nt][0], cfr[t][nt][1]);
            *(float2*)&bas[(row + 8) * BAS + colb] = make_float2(cfr[t][nt][2], cfr[t][nt][3]);
        }
    __syncthreads();

    // ---- a1 phase on CUDA cores (fp32, FFMA2 from constant) ----
    unsigned long long a1acc[7];
#pragma unroll
    for (int k = 0; k < 7; k++) a1acc[k] = 0ull;
    {
        const ulonglong2* trow = (const ulonglong2*)c_u1t;
#pragma unroll 4
        for (int i = 0; i < DIM; i++, trow += 4) {
            ulonglong2 q0 = trow[0];
            ulonglong2 q1 = trow[1];
            ulonglong2 q2 = trow[2];
            unsigned long long q3 = ((const unsigned long long*)trow)[6];
            unsigned long long y0 = dup2(xst[i * XST + tid]);
            fma2(a1acc[0], q0.x, y0);
            fma2(a1acc[1], q0.y, y0);
            fma2(a1acc[2], q1.x, y0);
            fma2(a1acc[3], q1.y, y0);
            fma2(a1acc[4], q2.x, y0);
            fma2(a1acc[5], q2.y, y0);
            fma2(a1acc[6], q3,   y0);
        }
    }

    // ---- fold: basis = a1*w1 + a2*w2 (in place in bas) ----
    const int LSEL[14] = {0, 1, 1, 1, 2, 2, 2, 2, 2, 2, 2, 2, 2, 0};
    {
        const int row = tid;
        int bb = blockIdx.x * NB + (row >> 6); if (bb >= B) bb = B - 1;
        const int cc = row & 63;
        float w10 = 0.f, w11 = 0.f, w12 = 0.f;
        float w20 = 0.f, w21 = 0.f, w22 = 0.f;
#pragma unroll
        for (int e = 0; e < 10; e++) {
            float a = __ldg(&attrs[bb * 10 + e]);
            w10 += a * __ldg(&W1_0[e * 64 + cc]);
            w20 += a * __ldg(&W2_0[e * 64 + cc]);
            w11 += a * __ldg(&W1_1[e * 64 + cc]);
            w21 += a * __ldg(&W2_1[e * 64 + cc]);
            w12 += a * __ldg(&W1_2[e * 64 + cc]);
            w22 += a * __ldg(&W2_2[e * 64 + cc]);
        }
        float w1v[3] = {w10, w11, w12};
        float w2v[3] = {w20, w21, w22};
        float* bp = bas + row * BAS;
#pragma unroll
        for (int k = 0; k < 7; k++) {
            float2 v1 = unpk2(a1acc[k]);
            int m0 = 2 * k, m1 = 2 * k + 1;
            bp[m0] = v1.x * w1v[LSEL[m0]] + bp[m0] * w2v[LSEL[m0]];
            if (m1 < 13)
                bp[m1] = v1.y * w1v[LSEL[m1]] + bp[m1] * w2v[LSEL[m1]];
        }
    }
    __syncthreads();

    // ---- Wlin cache into xst region (x no longer needed) ----
    {
        const float4* a0p = (const float4*)Wl0;
        const float4* a1p = (const float4*)Wl1;
        const float4* a2p = (const float4*)Wl2;
        float4* w4 = (float4*)wlS;
#pragma unroll
        for (int k = 0; k < 2; k++) {
            int idx = k * NT + tid;
            w4[idx]        = a0p[idx];
            w4[1024 + idx] = a1p[idx];
            w4[2048 + idx] = a2p[idx];
        }
    }
    __syncthreads();

    // ---- self-interaction: r[m] = sum_cc basis[b][cc][m] * Wlin_l[cc][c] ----
    const int g = tid >> 6;    // b-slot 0..7
    const int c = tid & 63;    // output channel
    float r[13];
#pragma unroll
    for (int m = 0; m < 13; m++) r[m] = 0.0f;

#pragma unroll 4
    for (int cc = 0; cc < 64; cc++) {
        float wv0 = wlS[cc * 64 + c];
        float wv1 = wlS[4096 + cc * 64 + c];
        float wv2 = wlS[8192 + cc * 64 + c];
        const float* br = bas + (g * 64 + cc) * BAS;
        float2 p0 = *(const float2*)(br);
        float2 p1 = *(const float2*)(br + 2);
        float2 p2 = *(const float2*)(br + 4);
        float2 p3 = *(const float2*)(br + 6);
        float2 p4 = *(const float2*)(br + 8);
        float2 p5 = *(const float2*)(br + 10);
        float  b12 = br[12];
        r[0]  += p0.x * wv0;
        r[1]  += p0.y * wv1;
        r[2]  += p1.x * wv1;
        r[3]  += p1.y * wv1;
        r[4]  += p2.x * wv2;
        r[5]  += p2.y * wv2;
        r[6]  += p3.x * wv2;
        r[7]  += p3.y * wv2;
        r[8]  += p4.x * wv2;
        r[9]  += p4.y * wv2;
        r[10] += p5.x * wv2;
        r[11] += p5.y * wv2;
        r[12] += b12  * wv2;
    }

    // ---- outputs: concat [out0 (B,C)] [out1 (B,C,3)] [out2 (B,C,9)] ----
    float* o0 = out;
    float* o1 = out + (size_t)B * 64;
    float* o2 = out + (size_t)B * 64 * 4;
    {
        int bb = blockIdx.x * NB + g;
        if (bb < B) {
            const int bo = bb * 64 + c;
            o0[bo] = r[0] + __ldg(&sc0[bo]);
#pragma unroll
            for (int k = 0; k < 3; k++)
                o1[bo * 3 + k] = r[1 + k] + __ldg(&sc1[bo * 3 + k]);
#pragma unroll
            for (int k = 0; k < 9; k++)
                o2[bo * 9 + k] = r[4 + k] + __ldg(&sc2[bo * 9 + k]);
        }
    }
}

extern "C" void kernel_launch(void* const* d_in, const int* in_sizes, int n_in,
                              void* d_out, int out_size) {
    const float* f0    = (const float*)d_in[0];
    const float* f1    = (const float*)d_in[1];
    const float* f2    = (const float*)d_in[2];
    const float* f3    = (const float*)d_in[3];
    const float* attrs = (const float*)d_in[4];
    const float* U2_0  = (const float*)d_in[5];
    const float* U1_0  = (const float*)d_in[6];
    const float* W1_0  = (const float*)d_in[7];
    const float* W2_0  = (const float*)d_in[8];
    const float* Wl0   = (const float*)d_in[9];
    const float* sc0   = (const float*)d_in[10];
    const float* U2_1  = (const float*)d_in[11];
    const float* U1_1  = (const float*)d_in[12];
    const float* W1_1  = (const float*)d_in[13];
    const float* W2_1  = (const float*)d_in[14];
    const float* Wl1   = (const float*)d_in[15];
    const float* sc1   = (const float*)d_in[16];
    const float* U2_2  = (const float*)d_in[17];
    const float* U1_2  = (const float*)d_in[18];
    const float* W1_2  = (const float*)d_in[19];
    const float* W2_2  = (const float*)d_in[20];
    const float* Wl2   = (const float*)d_in[21];
    const float* sc2   = (const float*)d_in[22];

    const int B = in_sizes[0] / 64;

    cudaFuncSetAttribute(main_kernel,
                         cudaFuncAttributeMaxDynamicSharedMemorySize, SMEM_BYTES);

    prep_kernel<<<(KP2 + DIM + 255) / 256, 256>>>(U2_0, U1_0, U2_1, U1_1, U2_2, U1_2);

    // copy staged U1 table into constant memory (graph-capturable D2D memcpy)
    void* src = nullptr;
    void* dst = nullptr;
    cudaGetSymbolAddress(&src, g_u1);
    cudaGetSymbolAddress(&dst, c_u1t);
    cudaMemcpyAsync(dst, src, DIM * 16 * sizeof(float),
                    cudaMemcpyDeviceToDevice, 0);

    const int grid = (B + NB - 1) / NB;
    main_kernel<<<grid, NT, SMEM_BYTES>>>(f0, f1, f2, f3, attrs,
                                          W1_0, W2_0, Wl0, sc0,
                                          W1_1, W2_1, Wl1, sc1,
                                          W1_2, W2_2, Wl2, sc2,
                                          (float*)d_out, B);
}